// round 2
// baseline (speedup 1.0000x reference)
#include <cuda_runtime.h>
#include <cuda_bf16.h>
#include <math.h>

#define NN 4096
#define EE 16384
#define PHID 64
#define EPSF 1e-8f

// Scratch: B = A * diag(f_mean) in bf16 (32MB, L2-resident), norms, fmean, sort perm.
__device__ __nv_bfloat16 g_B[(size_t)NN * NN];
__device__ float g_fmean[NN];
__device__ float g_d[NN];
__device__ int g_perm[2 * EE];

// ---------------------------------------------------------------------------
// k_aux: bid 0/1 = counting-sort edges of layer 0/1 by src; bid 2 = f_mean.
// ---------------------------------------------------------------------------
__global__ __launch_bounds__(1024) void k_aux(
    const int* __restrict__ src0, const int* __restrict__ src1,
    const float* __restrict__ f0, const float* __restrict__ f1) {
    int tid = threadIdx.x;
    if (blockIdx.x == 2) {
#pragma unroll
        for (int i = tid; i < NN; i += 1024)
            g_fmean[i] = 0.5f * (f0[i] + f1[i]);
        return;
    }
    const int* src = blockIdx.x ? src1 : src0;
    int* perm = g_perm + blockIdx.x * EE;

    __shared__ unsigned hist[NN];
    __shared__ unsigned wsum[32];
    for (int i = tid; i < NN; i += 1024) hist[i] = 0u;
    __syncthreads();
    for (int e = tid; e < EE; e += 1024) atomicAdd(&hist[src[e]], 1u);
    __syncthreads();

    // exclusive scan over 4096 bins (4 bins per thread + block scan)
    unsigned a = hist[tid * 4 + 0], b = hist[tid * 4 + 1];
    unsigned c = hist[tid * 4 + 2], d = hist[tid * 4 + 3];
    unsigned sum = a + b + c + d;
    int lane = tid & 31, wid = tid >> 5;
    unsigned x = sum;
#pragma unroll
    for (int o = 1; o < 32; o <<= 1) {
        unsigned y = __shfl_up_sync(0xffffffffu, x, o);
        if (lane >= o) x += y;
    }
    if (lane == 31) wsum[wid] = x;
    __syncthreads();
    if (wid == 0) {
        unsigned w = wsum[lane];
#pragma unroll
        for (int o = 1; o < 32; o <<= 1) {
            unsigned y = __shfl_up_sync(0xffffffffu, w, o);
            if (lane >= o) w += y;
        }
        wsum[lane] = w;
    }
    __syncthreads();
    unsigned base = wid ? wsum[wid - 1] : 0u;
    unsigned excl = x + base - sum;
    hist[tid * 4 + 0] = excl;
    hist[tid * 4 + 1] = excl + a;
    hist[tid * 4 + 2] = excl + a + b;
    hist[tid * 4 + 3] = excl + a + b + c;
    __syncthreads();

    for (int e = tid; e < EE; e += 1024) {
        unsigned pos = atomicAdd(&hist[src[e]], 1u);
        perm[pos] = e;
    }
}

// ---------------------------------------------------------------------------
// k_prep: 4 rows per CTA; scale by f_mean (smem), write bf16 B, fp32 norms.
// ---------------------------------------------------------------------------
__global__ __launch_bounds__(256) void k_prep(const float* __restrict__ A) {
    __shared__ float fsm[NN];
    __shared__ float red[8];
    for (int i = threadIdx.x; i < NN; i += 256) fsm[i] = g_fmean[i];
    __syncthreads();
    const float4* f4 = (const float4*)fsm;

#pragma unroll
    for (int r = 0; r < 4; ++r) {
        int row = blockIdx.x * 4 + r;
        const float4* a4 = (const float4*)(A + (size_t)row * NN);
        uint2* b4 = (uint2*)(g_B + (size_t)row * NN);
        float acc = 0.f;
#pragma unroll
        for (int it = 0; it < 4; ++it) {
            int q = threadIdx.x + it * 256;
            float4 v = a4[q];
            float4 f = f4[q];
            float m0 = v.x * f.x, m1 = v.y * f.y, m2 = v.z * f.z, m3 = v.w * f.w;
            float e0 = m0 + EPSF, e1 = m1 + EPSF, e2 = m2 + EPSF, e3 = m3 + EPSF;
            acc += e0 * e0 + e1 * e1;
            acc += e2 * e2 + e3 * e3;
            __nv_bfloat162 p0 = __floats2bfloat162_rn(m0, m1);
            __nv_bfloat162 p1 = __floats2bfloat162_rn(m2, m3);
            uint2 o;
            o.x = *(unsigned*)&p0;
            o.y = *(unsigned*)&p1;
            b4[q] = o;
        }
#pragma unroll
        for (int off = 16; off; off >>= 1)
            acc += __shfl_xor_sync(0xffffffffu, acc, off);
        int wid = threadIdx.x >> 5, lane = threadIdx.x & 31;
        if (lane == 0) red[wid] = acc;
        __syncthreads();
        if (threadIdx.x == 0) {
            float t = 0.f;
#pragma unroll
            for (int w = 0; w < 8; w++) t += red[w];
            g_d[row] = sqrtf(t);
        }
        __syncthreads();
    }
}

__device__ __forceinline__ float b2lo(unsigned u) { return __uint_as_float(u << 16); }
__device__ __forceinline__ float b2hi(unsigned u) { return __uint_as_float(u & 0xffff0000u); }

// ---------------------------------------------------------------------------
// k_edge: one warp per (sorted) edge. Src-sorted order => L1 reuse of src rows
// within the CTA (16 warps). bf16 dot from L2-resident B, then 2 tiny MLPs.
// ---------------------------------------------------------------------------
__global__ __launch_bounds__(512) void k_edge(
    const int* __restrict__ src0, const int* __restrict__ dst0,
    const int* __restrict__ src1, const int* __restrict__ dst1,
    const float* __restrict__ p1w1, const float* __restrict__ p1b1,
    const float* __restrict__ p1w2, const float* __restrict__ p1b2,
    const float* __restrict__ p2w1, const float* __restrict__ p2b1,
    const float* __restrict__ p2w2, const float* __restrict__ p2b2,
    float* __restrict__ out) {
    int gw = (int)((blockIdx.x * blockDim.x + threadIdx.x) >> 5);
    int lane = threadIdx.x & 31;
    int layer = gw >> 14;          // / EE
    int slot = gw & (EE - 1);
    int e = g_perm[layer * EE + slot];
    int s = layer ? __ldg(src1 + e) : __ldg(src0 + e);
    int t = layer ? __ldg(dst1 + e) : __ldg(dst0 + e);

    const uint4* ps = (const uint4*)(g_B + (size_t)s * NN) + lane;
    const uint4* pt = (const uint4*)(g_B + (size_t)t * NN) + lane;

    float a0 = 0.f, a1 = 0.f, a2 = 0.f, a3 = 0.f;
#pragma unroll
    for (int k = 0; k < 16; k++) {
        uint4 a = ps[k * 32];
        uint4 b = pt[k * 32];
        a0 = fmaf(b2lo(a.x), b2lo(b.x), a0);
        a0 = fmaf(b2hi(a.x), b2hi(b.x), a0);
        a1 = fmaf(b2lo(a.y), b2lo(b.y), a1);
        a1 = fmaf(b2hi(a.y), b2hi(b.y), a1);
        a2 = fmaf(b2lo(a.z), b2lo(b.z), a2);
        a2 = fmaf(b2hi(a.z), b2hi(b.z), a2);
        a3 = fmaf(b2lo(a.w), b2lo(b.w), a3);
        a3 = fmaf(b2hi(a.w), b2hi(b.w), a3);
    }
    float acc = (a0 + a1) + (a2 + a3);
#pragma unroll
    for (int off = 16; off; off >>= 1)
        acc += __shfl_xor_sync(0xffffffffu, acc, off);

    float x = acc / (g_d[s] * g_d[t]);

    int o = layer * PHID;
    // MLP 1: 1 -> 64 -> 1 (2 hidden units per lane)
    float h0 = fmaxf(fmaf(x, p1w1[o + lane], p1b1[o + lane]), 0.f);
    float h1 = fmaxf(fmaf(x, p1w1[o + lane + 32], p1b1[o + lane + 32]), 0.f);
    float y = fmaf(h0, p1w2[o + lane], h1 * p1w2[o + lane + 32]);
#pragma unroll
    for (int off = 16; off; off >>= 1)
        y += __shfl_xor_sync(0xffffffffu, y, off);
    y += p1b2[layer];
    float x2 = 0.5f * y;  // BETA * y / LM

    // MLP 2
    float g0 = fmaxf(fmaf(x2, p2w1[o + lane], p2b1[o + lane]), 0.f);
    float g1 = fmaxf(fmaf(x2, p2w1[o + lane + 32], p2b1[o + lane + 32]), 0.f);
    float z = fmaf(g0, p2w2[o + lane], g1 * p2w2[o + lane + 32]);
#pragma unroll
    for (int off = 16; off; off >>= 1)
        z += __shfl_xor_sync(0xffffffffu, z, off);
    z += p2b2[layer];

    if (lane == 0) out[layer * EE + e] = z;
}

extern "C" void kernel_launch(void* const* d_in, const int* in_sizes, int n_in,
                              void* d_out, int out_size) {
    const float* A    = (const float*)d_in[0];
    const int* src0   = (const int*)d_in[1];
    const int* dst0   = (const int*)d_in[2];
    const int* src1   = (const int*)d_in[3];
    const int* dst1   = (const int*)d_in[4];
    const float* f0   = (const float*)d_in[5];
    const float* f1   = (const float*)d_in[6];
    const float* p1w1 = (const float*)d_in[7];
    const float* p1b1 = (const float*)d_in[8];
    const float* p1w2 = (const float*)d_in[9];
    const float* p1b2 = (const float*)d_in[10];
    const float* p2w1 = (const float*)d_in[11];
    const float* p2b1 = (const float*)d_in[12];
    const float* p2w2 = (const float*)d_in[13];
    const float* p2b2 = (const float*)d_in[14];
    float* out = (float*)d_out;

    k_aux<<<3, 1024>>>(src0, src1, f0, f1);
    k_prep<<<NN / 4, 256>>>(A);
    k_edge<<<(2 * EE) / 16, 512>>>(src0, dst0, src1, dst1,
                                   p1w1, p1b1, p1w2, p1b2,
                                   p2w1, p2b1, p2w2, p2b2, out);
}

// round 3
// speedup vs baseline: 1.5274x; 1.5274x over previous
#include <cuda_runtime.h>
#include <cuda_bf16.h>
#include <math.h>

#define NN 4096
#define EE 16384
#define PHID 64
#define EPSF 1e-8f

// Scratch: Q = round(B/scale_r) int8 (16MB, L2-resident); per-row c = scale_r/d_r.
__device__ char g_Q[(size_t)NN * NN];
__device__ float g_c[NN];

// ---------------------------------------------------------------------------
// k_prep: 4 rows per CTA. Computes f_mean into smem (fused), holds each row's
// scaled values in registers, computes fp32 norm + row max, quantizes to int8.
// ---------------------------------------------------------------------------
__global__ __launch_bounds__(256) void k_prep(const float* __restrict__ A,
                                              const float* __restrict__ f0,
                                              const float* __restrict__ f1) {
    __shared__ float fsm[NN];
    __shared__ float rsum[8];
    __shared__ float rmax[8];
    __shared__ float bcast;
    for (int i = threadIdx.x; i < NN; i += 256)
        fsm[i] = 0.5f * (f0[i] + f1[i]);
    __syncthreads();
    const float4* f4 = (const float4*)fsm;
    int wid = threadIdx.x >> 5, lane = threadIdx.x & 31;

#pragma unroll
    for (int r = 0; r < 4; ++r) {
        int row = blockIdx.x * 4 + r;
        const float4* a4 = (const float4*)(A + (size_t)row * NN);
        float4 m[4];
        float acc = 0.f, vmax = 0.f;
#pragma unroll
        for (int it = 0; it < 4; ++it) {
            int q = threadIdx.x + it * 256;
            float4 v = a4[q];
            float4 f = f4[q];
            m[it].x = v.x * f.x; m[it].y = v.y * f.y;
            m[it].z = v.z * f.z; m[it].w = v.w * f.w;
            float e0 = m[it].x + EPSF, e1 = m[it].y + EPSF;
            float e2 = m[it].z + EPSF, e3 = m[it].w + EPSF;
            acc += e0 * e0 + e1 * e1 + e2 * e2 + e3 * e3;
            vmax = fmaxf(vmax, fmaxf(fmaxf(fabsf(m[it].x), fabsf(m[it].y)),
                                     fmaxf(fabsf(m[it].z), fabsf(m[it].w))));
        }
#pragma unroll
        for (int off = 16; off; off >>= 1) {
            acc += __shfl_xor_sync(0xffffffffu, acc, off);
            vmax = fmaxf(vmax, __shfl_xor_sync(0xffffffffu, vmax, off));
        }
        if (lane == 0) { rsum[wid] = acc; rmax[wid] = vmax; }
        __syncthreads();
        if (threadIdx.x == 0) {
            float t = 0.f, mx = 0.f;
#pragma unroll
            for (int w = 0; w < 8; w++) { t += rsum[w]; mx = fmaxf(mx, rmax[w]); }
            float scale = fmaxf(mx, 1e-20f) * (1.0f / 127.0f);
            g_c[row] = scale / sqrtf(t);
            bcast = 1.0f / scale;
        }
        __syncthreads();
        float inv_scale = bcast;
        // quantize: 16 values/thread -> one uint4 (16 int8) store
        uchar4 pk[4];
#pragma unroll
        for (int it = 0; it < 4; ++it) {
            int q0 = __float2int_rn(m[it].x * inv_scale);
            int q1 = __float2int_rn(m[it].y * inv_scale);
            int q2 = __float2int_rn(m[it].z * inv_scale);
            int q3 = __float2int_rn(m[it].w * inv_scale);
            pk[it].x = (unsigned char)(char)max(-127, min(127, q0));
            pk[it].y = (unsigned char)(char)max(-127, min(127, q1));
            pk[it].z = (unsigned char)(char)max(-127, min(127, q2));
            pk[it].w = (unsigned char)(char)max(-127, min(127, q3));
        }
        uint4 o;
        o.x = *(unsigned*)&pk[0]; o.y = *(unsigned*)&pk[1];
        o.z = *(unsigned*)&pk[2]; o.w = *(unsigned*)&pk[3];
        // each float4-group it covers cols [it*1024 + tid*4 .. +3] -> int8 bytes
        // pack layout must match read layout: bytes [tid*16 .. tid*16+15] hold
        // cols {tid*4+it*1024}. Reads are a plain dot over the full row, and
        // BOTH rows of an edge use the same permutation, so any fixed
        // column permutation is dot-invariant. (norm likewise permutation-inv)
        ((uint4*)(g_Q + (size_t)row * NN))[threadIdx.x] = o;
        __syncthreads();
    }
}

// ---------------------------------------------------------------------------
// k_edge: one warp per edge; exact int8 dot via dp4a, scale by c_s*c_t, MLPs.
// ---------------------------------------------------------------------------
__global__ __launch_bounds__(512) void k_edge(
    const int* __restrict__ src0, const int* __restrict__ dst0,
    const int* __restrict__ src1, const int* __restrict__ dst1,
    const float* __restrict__ p1w1, const float* __restrict__ p1b1,
    const float* __restrict__ p1w2, const float* __restrict__ p1b2,
    const float* __restrict__ p2w1, const float* __restrict__ p2b1,
    const float* __restrict__ p2w2, const float* __restrict__ p2b2,
    float* __restrict__ out) {
    int gw = (int)((blockIdx.x * blockDim.x + threadIdx.x) >> 5);
    int lane = threadIdx.x & 31;
    int layer = gw >> 14;          // / EE
    int e = gw & (EE - 1);
    int s = layer ? __ldg(src1 + e) : __ldg(src0 + e);
    int t = layer ? __ldg(dst1 + e) : __ldg(dst0 + e);

    const uint4* ps = (const uint4*)(g_Q + (size_t)s * NN) + lane;
    const uint4* pt = (const uint4*)(g_Q + (size_t)t * NN) + lane;

    int acc = 0;
#pragma unroll
    for (int k = 0; k < 8; k++) {
        uint4 a = ps[k * 32];
        uint4 b = pt[k * 32];
        acc = __dp4a((int)a.x, (int)b.x, acc);
        acc = __dp4a((int)a.y, (int)b.y, acc);
        acc = __dp4a((int)a.z, (int)b.z, acc);
        acc = __dp4a((int)a.w, (int)b.w, acc);
    }
#pragma unroll
    for (int off = 16; off; off >>= 1)
        acc += __shfl_xor_sync(0xffffffffu, acc, off);

    float x = (float)acc * g_c[s] * g_c[t];

    int o = layer * PHID;
    // MLP 1: 1 -> 64 -> 1 (2 hidden units per lane)
    float h0 = fmaxf(fmaf(x, p1w1[o + lane], p1b1[o + lane]), 0.f);
    float h1 = fmaxf(fmaf(x, p1w1[o + lane + 32], p1b1[o + lane + 32]), 0.f);
    float y = fmaf(h0, p1w2[o + lane], h1 * p1w2[o + lane + 32]);
#pragma unroll
    for (int off = 16; off; off >>= 1)
        y += __shfl_xor_sync(0xffffffffu, y, off);
    y += p1b2[layer];
    float x2 = 0.5f * y;  // BETA * y / LM

    // MLP 2
    float g0 = fmaxf(fmaf(x2, p2w1[o + lane], p2b1[o + lane]), 0.f);
    float g1 = fmaxf(fmaf(x2, p2w1[o + lane + 32], p2b1[o + lane + 32]), 0.f);
    float z = fmaf(g0, p2w2[o + lane], g1 * p2w2[o + lane + 32]);
#pragma unroll
    for (int off = 16; off; off >>= 1)
        z += __shfl_xor_sync(0xffffffffu, z, off);
    z += p2b2[layer];

    if (lane == 0) out[gw] = z;
}

extern "C" void kernel_launch(void* const* d_in, const int* in_sizes, int n_in,
                              void* d_out, int out_size) {
    const float* A    = (const float*)d_in[0];
    const int* src0   = (const int*)d_in[1];
    const int* dst0   = (const int*)d_in[2];
    const int* src1   = (const int*)d_in[3];
    const int* dst1   = (const int*)d_in[4];
    const float* f0   = (const float*)d_in[5];
    const float* f1   = (const float*)d_in[6];
    const float* p1w1 = (const float*)d_in[7];
    const float* p1b1 = (const float*)d_in[8];
    const float* p1w2 = (const float*)d_in[9];
    const float* p1b2 = (const float*)d_in[10];
    const float* p2w1 = (const float*)d_in[11];
    const float* p2b1 = (const float*)d_in[12];
    const float* p2w2 = (const float*)d_in[13];
    const float* p2b2 = (const float*)d_in[14];
    float* out = (float*)d_out;

    k_prep<<<NN / 4, 256>>>(A, f0, f1);
    k_edge<<<(2 * EE) / 16, 512>>>(src0, dst0, src1, dst1,
                                   p1w1, p1b1, p1w2, p1b2,
                                   p2w1, p2b1, p2w2, p2b2, out);
}

// round 4
// speedup vs baseline: 1.6216x; 1.0616x over previous
#include <cuda_runtime.h>
#include <cuda_bf16.h>
#include <math.h>

#define NN 4096
#define EE 16384
#define PHID 64
#define EPSF 1e-8f

// Scratch: Q = round(B/scale_r) int8 (16MB, L2-resident); per-row c = scale_r/d_r.
__device__ char g_Q[(size_t)NN * NN];
__device__ float g_c[NN];

// ---------------------------------------------------------------------------
// k_prep: 4 rows per CTA, all loaded upfront into registers (MLP~24).
// f_mean lives in registers (same 16 cols per thread for every row).
// One fused block-reduction (4 sums + 4 maxes), 2 barriers total.
// ---------------------------------------------------------------------------
__global__ __launch_bounds__(256) void k_prep(const float* __restrict__ A,
                                              const float* __restrict__ f0,
                                              const float* __restrict__ f1) {
    __shared__ float rsum[4][8];
    __shared__ float rmax[4][8];
    __shared__ float s_cinv[4];
    int tid = threadIdx.x;
    int wid = tid >> 5, lane = tid & 31;

    // f_mean for this thread's 16 columns, in registers
    float4 f[4];
#pragma unroll
    for (int it = 0; it < 4; ++it) {
        int q = tid + it * 256;
        float4 a = ((const float4*)f0)[q];
        float4 b = ((const float4*)f1)[q];
        f[it].x = 0.5f * (a.x + b.x);
        f[it].y = 0.5f * (a.y + b.y);
        f[it].z = 0.5f * (a.z + b.z);
        f[it].w = 0.5f * (a.w + b.w);
    }

    // load + scale all 4 rows upfront
    float4 m[4][4];
    float acc[4], vmax[4];
#pragma unroll
    for (int r = 0; r < 4; ++r) {
        int row = blockIdx.x * 4 + r;
        const float4* a4 = (const float4*)(A + (size_t)row * NN);
        acc[r] = 0.f;
        vmax[r] = 0.f;
#pragma unroll
        for (int it = 0; it < 4; ++it) {
            float4 v = a4[tid + it * 256];
            m[r][it].x = v.x * f[it].x;
            m[r][it].y = v.y * f[it].y;
            m[r][it].z = v.z * f[it].z;
            m[r][it].w = v.w * f[it].w;
            float e0 = m[r][it].x + EPSF, e1 = m[r][it].y + EPSF;
            float e2 = m[r][it].z + EPSF, e3 = m[r][it].w + EPSF;
            acc[r] += e0 * e0 + e1 * e1 + e2 * e2 + e3 * e3;
            vmax[r] = fmaxf(vmax[r],
                            fmaxf(fmaxf(fabsf(m[r][it].x), fabsf(m[r][it].y)),
                                  fmaxf(fabsf(m[r][it].z), fabsf(m[r][it].w))));
        }
    }

    // fused warp reduction of 8 values
#pragma unroll
    for (int off = 16; off; off >>= 1) {
#pragma unroll
        for (int r = 0; r < 4; ++r) {
            acc[r] += __shfl_xor_sync(0xffffffffu, acc[r], off);
            vmax[r] = fmaxf(vmax[r], __shfl_xor_sync(0xffffffffu, vmax[r], off));
        }
    }
    if (lane == 0) {
#pragma unroll
        for (int r = 0; r < 4; ++r) {
            rsum[r][wid] = acc[r];
            rmax[r][wid] = vmax[r];
        }
    }
    __syncthreads();
    if (tid < 4) {
        float t = 0.f, mx = 0.f;
#pragma unroll
        for (int w = 0; w < 8; w++) {
            t += rsum[tid][w];
            mx = fmaxf(mx, rmax[tid][w]);
        }
        float scale = fmaxf(mx, 1e-20f) * (1.0f / 127.0f);
        g_c[blockIdx.x * 4 + tid] = scale / sqrtf(t);
        s_cinv[tid] = 1.0f / scale;
    }
    __syncthreads();

    // quantize + store all 4 rows (column permutation is dot/norm-invariant
    // since both rows of every edge use the same packing)
#pragma unroll
    for (int r = 0; r < 4; ++r) {
        float inv_scale = s_cinv[r];
        uchar4 pk[4];
#pragma unroll
        for (int it = 0; it < 4; ++it) {
            int q0 = __float2int_rn(m[r][it].x * inv_scale);
            int q1 = __float2int_rn(m[r][it].y * inv_scale);
            int q2 = __float2int_rn(m[r][it].z * inv_scale);
            int q3 = __float2int_rn(m[r][it].w * inv_scale);
            pk[it].x = (unsigned char)(char)max(-127, min(127, q0));
            pk[it].y = (unsigned char)(char)max(-127, min(127, q1));
            pk[it].z = (unsigned char)(char)max(-127, min(127, q2));
            pk[it].w = (unsigned char)(char)max(-127, min(127, q3));
        }
        uint4 o;
        o.x = *(unsigned*)&pk[0];
        o.y = *(unsigned*)&pk[1];
        o.z = *(unsigned*)&pk[2];
        o.w = *(unsigned*)&pk[3];
        ((uint4*)(g_Q + (size_t)(blockIdx.x * 4 + r) * NN))[tid] = o;
    }
}

// ---------------------------------------------------------------------------
// k_edge: one warp per edge; exact int8 dot via dp4a (4 independent
// accumulators), REDUX.SUM reduction, scale by c_s*c_t, two tiny MLPs.
// ---------------------------------------------------------------------------
__global__ __launch_bounds__(512) void k_edge(
    const int* __restrict__ src0, const int* __restrict__ dst0,
    const int* __restrict__ src1, const int* __restrict__ dst1,
    const float* __restrict__ p1w1, const float* __restrict__ p1b1,
    const float* __restrict__ p1w2, const float* __restrict__ p1b2,
    const float* __restrict__ p2w1, const float* __restrict__ p2b1,
    const float* __restrict__ p2w2, const float* __restrict__ p2b2,
    float* __restrict__ out) {
    int gw = (int)((blockIdx.x * blockDim.x + threadIdx.x) >> 5);
    int lane = threadIdx.x & 31;
    int layer = gw >> 14;  // / EE
    int e = gw & (EE - 1);
    int s = layer ? __ldg(src1 + e) : __ldg(src0 + e);
    int t = layer ? __ldg(dst1 + e) : __ldg(dst0 + e);

    const uint4* ps = (const uint4*)(g_Q + (size_t)s * NN) + lane;
    const uint4* pt = (const uint4*)(g_Q + (size_t)t * NN) + lane;

    int acc0 = 0, acc1 = 0, acc2 = 0, acc3 = 0;
#pragma unroll
    for (int k = 0; k < 8; k++) {
        uint4 a = ps[k * 32];
        uint4 b = pt[k * 32];
        acc0 = __dp4a((int)a.x, (int)b.x, acc0);
        acc1 = __dp4a((int)a.y, (int)b.y, acc1);
        acc2 = __dp4a((int)a.z, (int)b.z, acc2);
        acc3 = __dp4a((int)a.w, (int)b.w, acc3);
    }
    int acc = (acc0 + acc1) + (acc2 + acc3);
    acc = __reduce_add_sync(0xffffffffu, acc);

    float x = (float)acc * g_c[s] * g_c[t];

    int o = layer * PHID;
    // MLP 1: 1 -> 64 -> 1 (2 hidden units per lane)
    float h0 = fmaxf(fmaf(x, p1w1[o + lane], p1b1[o + lane]), 0.f);
    float h1 = fmaxf(fmaf(x, p1w1[o + lane + 32], p1b1[o + lane + 32]), 0.f);
    float y = fmaf(h0, p1w2[o + lane], h1 * p1w2[o + lane + 32]);
#pragma unroll
    for (int off = 16; off; off >>= 1)
        y += __shfl_xor_sync(0xffffffffu, y, off);
    y += p1b2[layer];
    float x2 = 0.5f * y;  // BETA * y / LM

    // MLP 2
    float g0 = fmaxf(fmaf(x2, p2w1[o + lane], p2b1[o + lane]), 0.f);
    float g1 = fmaxf(fmaf(x2, p2w1[o + lane + 32], p2b1[o + lane + 32]), 0.f);
    float z = fmaf(g0, p2w2[o + lane], g1 * p2w2[o + lane + 32]);
#pragma unroll
    for (int off = 16; off; off >>= 1)
        z += __shfl_xor_sync(0xffffffffu, z, off);
    z += p2b2[layer];

    if (lane == 0) out[gw] = z;
}

extern "C" void kernel_launch(void* const* d_in, const int* in_sizes, int n_in,
                              void* d_out, int out_size) {
    const float* A    = (const float*)d_in[0];
    const int* src0   = (const int*)d_in[1];
    const int* dst0   = (const int*)d_in[2];
    const int* src1   = (const int*)d_in[3];
    const int* dst1   = (const int*)d_in[4];
    const float* f0   = (const float*)d_in[5];
    const float* f1   = (const float*)d_in[6];
    const float* p1w1 = (const float*)d_in[7];
    const float* p1b1 = (const float*)d_in[8];
    const float* p1w2 = (const float*)d_in[9];
    const float* p1b2 = (const float*)d_in[10];
    const float* p2w1 = (const float*)d_in[11];
    const float* p2b1 = (const float*)d_in[12];
    const float* p2w2 = (const float*)d_in[13];
    const float* p2b2 = (const float*)d_in[14];
    float* out = (float*)d_out;

    k_prep<<<NN / 4, 256>>>(A, f0, f1);
    k_edge<<<(2 * EE) / 16, 512>>>(src0, dst0, src1, dst1,
                                   p1w1, p1b1, p1w2, p1b2,
                                   p2w1, p2b1, p2w2, p2b2, out);
}